// round 14
// baseline (speedup 1.0000x reference)
#include <cuda_runtime.h>
#include <cuda_fp16.h>
#include <math.h>
#include <stdint.h>

// Problem constants
#define BATCH 4
#define SEQ   4096
#define DMODEL 1024
#define MTOT  (BATCH * SEQ)          // 16384
#define SCALE_INV (1.0f / 32.0f)     // 1/sqrt(1024)

// GEMM tile config (fp16 NT, mma.sync m16n8k16, 4 warps x (64x64) warp tiles)
#define BM 128
#define BN 128
#define BK 64
#define GTHREADS 128
#define NSTAGE 3
#define LDH   72
#define LDH32 36
#define ROWB  144
#define TILE_BYTES (128 * ROWB)       // 18432
#define STAGE_BYTES (2 * TILE_BYTES)  // 36864
#define SMEM_BYTES (NSTAGE * STAGE_BYTES)  // 110592
#define TLD 132                       // fp32 transpose-stage stride (4 mod 32)

// Scratch
__device__ __half g_Xh[MTOT * DMODEL];                     // 32 MB  half(x)
__device__ __half g_Wh[3 * DMODEL * DMODEL];               // 6 MB   half(W)
__device__ __half g_QKVh[2 * MTOT * DMODEL];               // 64 MB  half Q,K
__device__ __half g_Vt[(size_t)BATCH * DMODEL * SEQ];      // 32 MB  V transposed [b][d][t]
__device__ float  g_S[(size_t)BATCH * SEQ * SEQ];          // 256 MB scores fp32
__device__ __half g_P[(size_t)BATCH * SEQ * SEQ];          // 128 MB probs half

// ---------------------------------------------------------------------------
// Helpers
// ---------------------------------------------------------------------------
__device__ __forceinline__ uint32_t smem_u32(const void* p) {
    return (uint32_t)__cvta_generic_to_shared(p);
}
__device__ __forceinline__ void cp_async16(uint32_t s, const void* g) {
    asm volatile("cp.async.cg.shared.global [%0], [%1], 16;" :: "r"(s), "l"(g));
}
#define CP_COMMIT() asm volatile("cp.async.commit_group;")
#define CP_WAIT1()  asm volatile("cp.async.wait_group 1;")

__device__ __forceinline__ void mma_f16(float* c, const uint32_t* a, const uint32_t* b) {
    asm volatile(
        "mma.sync.aligned.m16n8k16.row.col.f32.f16.f16.f32 "
        "{%0,%1,%2,%3}, {%4,%5,%6,%7}, {%8,%9}, {%0,%1,%2,%3};"
        : "+f"(c[0]), "+f"(c[1]), "+f"(c[2]), "+f"(c[3])
        : "r"(a[0]), "r"(a[1]), "r"(a[2]), "r"(a[3]), "r"(b[0]), "r"(b[1]));
}
__device__ __forceinline__ void ldsm_x4(uint32_t* r, uint32_t addr) {
    asm volatile("ldmatrix.sync.aligned.m8n8.x4.shared.b16 {%0,%1,%2,%3}, [%4];"
        : "=r"(r[0]), "=r"(r[1]), "=r"(r[2]), "=r"(r[3]) : "r"(addr));
}

// Fill one 128x64-half tile (NT: rows contiguous in K) into stage buffer.
__device__ __forceinline__ void cpa_h(uint32_t Sdst, const __half* G,
                                      int row0, int k0, int ldg, int tid) {
    #pragma unroll
    for (int i = 0; i < 8; i++) {
        int f = tid + i * GTHREADS;
        int row = f >> 3;
        int cb = (f & 7) * 16;
        cp_async16(Sdst + (uint32_t)(row * ROWB + cb),
                   &G[(size_t)(row0 + row) * ldg + k0 + (cb >> 1)]);
    }
}

// MMA over one BK=64 chunk, 64x64 warp tile, ldmatrix operands.
// Lane->fragment mapping identical to the numerically-verified scalar loads.
__device__ __forceinline__ void mma_block_h(uint32_t Abase, uint32_t Bbase,
                                            float c[4][8][4], int wm, int wn, int lane) {
    const uint32_t aoff = Abase + (uint32_t)(wm + (lane & 15)) * ROWB + (lane >> 4) * 16;
    const uint32_t boff = Bbase + (uint32_t)(wn + ((lane >> 4) * 8) + (lane & 7)) * ROWB
                        + ((lane >> 3) & 1) * 16;
    #pragma unroll
    for (int ks = 0; ks < 4; ks++) {
        uint32_t a[4][4], b[8][2];
        #pragma unroll
        for (int i = 0; i < 4; i++)
            ldsm_x4(a[i], aoff + (uint32_t)i * (16 * ROWB) + ks * 32);
        #pragma unroll
        for (int jp = 0; jp < 4; jp++) {
            uint32_t t[4];
            ldsm_x4(t, boff + (uint32_t)jp * (16 * ROWB) + ks * 32);
            b[2 * jp][0] = t[0]; b[2 * jp][1] = t[1];
            b[2 * jp + 1][0] = t[2]; b[2 * jp + 1][1] = t[3];
        }
        #pragma unroll
        for (int i = 0; i < 4; i++)
            #pragma unroll
            for (int j = 0; j < 8; j++)
                mma_f16(c[i][j], a[i], b[j]);
    }
}

// Shared NT fp16 mainloop (one barrier/iter, early next-next-stage prefetch).
__device__ __forceinline__ void nt_gemm_h(const __half* A, const __half* B,
                                          int ldga, int ldgb, int m0, int n0, int kt,
                                          float c[4][8][4], int tid, int wm, int wn, int lane) {
    extern __shared__ __align__(16) unsigned char dsm[];
    const uint32_t sb = smem_u32(dsm);

    #pragma unroll
    for (int s = 0; s < NSTAGE - 1; s++) {
        cpa_h(sb + s * STAGE_BYTES,              A, m0, s * BK, ldga, tid);
        cpa_h(sb + s * STAGE_BYTES + TILE_BYTES, B, n0, s * BK, ldgb, tid);
        CP_COMMIT();
    }
    for (int it = 0; it < kt; it++) {
        CP_WAIT1();
        __syncthreads();
        const int nc = it + NSTAGE - 1;
        if (nc < kt) {
            const int nb = nc % NSTAGE;
            cpa_h(sb + nb * STAGE_BYTES,              A, m0, nc * BK, ldga, tid);
            cpa_h(sb + nb * STAGE_BYTES + TILE_BYTES, B, n0, nc * BK, ldgb, tid);
        }
        CP_COMMIT();
        const int buf = it % NSTAGE;
        mma_block_h(sb + buf * STAGE_BYTES, sb + buf * STAGE_BYTES + TILE_BYTES,
                    c, wm, wn, lane);
    }
}

#define ZERO_ACC(c)                                   \
    _Pragma("unroll")                                 \
    for (int i = 0; i < 4; i++)                       \
        _Pragma("unroll")                             \
        for (int j = 0; j < 8; j++)                   \
            _Pragma("unroll")                         \
            for (int t = 0; t < 4; t++) c[i][j][t] = 0.0f;

// ---------------------------------------------------------------------------
// Kernel 0a/0b: fp32 -> fp16 convert (x; and the three W's in one launch)
// ---------------------------------------------------------------------------
__global__ __launch_bounds__(256)
void roundh_kernel(const float* __restrict__ in, __half* __restrict__ out, int n4)
{
    int i = blockIdx.x * 256 + threadIdx.x;
    if (i < n4) {
        float4 v = ((const float4*)in)[i];
        __half2 h0 = __floats2half2_rn(v.x, v.y);
        __half2 h1 = __floats2half2_rn(v.z, v.w);
        ((uint2*)out)[i] = make_uint2(*(uint32_t*)&h0, *(uint32_t*)&h1);
    }
}

__global__ __launch_bounds__(256)
void roundhW_kernel(const float* __restrict__ Wq, const float* __restrict__ Wk,
                    const float* __restrict__ Wv, int n4)
{
    const int z = blockIdx.y;
    const float* in = (z == 0) ? Wq : (z == 1) ? Wk : Wv;
    __half* out = g_Wh + (size_t)z * DMODEL * DMODEL;
    int i = blockIdx.x * 256 + threadIdx.x;
    if (i < n4) {
        float4 v = ((const float4*)in)[i];
        __half2 h0 = __floats2half2_rn(v.x, v.y);
        __half2 h1 = __floats2half2_rn(v.z, v.w);
        ((uint2*)out)[i] = make_uint2(*(uint32_t*)&h0, *(uint32_t*)&h1);
    }
}

// ---------------------------------------------------------------------------
// Kernel 1: QKV projection. z<2: out = half(x@W^T + b) to g_QKVh.
//           z==2: V tile transposed through smem -> g_Vt only.
// ---------------------------------------------------------------------------
__global__ __launch_bounds__(GTHREADS, 2)
void qkv_kernel(const float* __restrict__ bq,
                const float* __restrict__ bk,
                const float* __restrict__ bv)
{
    const int z = blockIdx.z;
    const __half* W    = g_Wh + (size_t)z * DMODEL * DMODEL;
    const float*  bias = (z == 0) ? bq : (z == 1) ? bk : bv;

    const int tid  = threadIdx.x;
    const int lane = tid & 31;
    const int warp = tid >> 5;
    const int wm = (warp & 1) * 64;
    const int wn = (warp >> 1) * 64;
    const int m0 = blockIdx.y * BM;
    const int n0 = blockIdx.x * BN;

    float c[4][8][4];
    ZERO_ACC(c)

    nt_gemm_h(g_Xh, W, DMODEL, DMODEL, m0, n0, DMODEL / BK, c, tid, wm, wn, lane);

    const int gr = lane >> 2, gc = lane & 3;
    if (z < 2) {
        __half* out = g_QKVh + (size_t)z * (MTOT * DMODEL);
        #pragma unroll
        for (int i = 0; i < 4; i++) {
            int r0 = m0 + wm + i * 16 + gr;
            #pragma unroll
            for (int j = 0; j < 8; j++) {
                int cn = n0 + wn + j * 8 + gc * 2;
                float2 bb = *(const float2*)&bias[cn];
                __half2 h0 = __floats2half2_rn(c[i][j][0] + bb.x, c[i][j][1] + bb.y);
                __half2 h1 = __floats2half2_rn(c[i][j][2] + bb.x, c[i][j][3] + bb.y);
                *(__half2*)&out[(size_t)r0 * DMODEL + cn] = h0;
                *(__half2*)&out[(size_t)(r0 + 8) * DMODEL + cn] = h1;
            }
        }
    } else {
        // V: stage fp32 tile transposed in smem, then coalesced half writes to Vt.
        extern __shared__ __align__(16) unsigned char dsm[];
        float* tsf = (float*)dsm;   // 128 x TLD floats
        __syncthreads();            // mainloop smem reads done
        #pragma unroll
        for (int i = 0; i < 4; i++) {
            int r0 = wm + i * 16 + gr;
            #pragma unroll
            for (int j = 0; j < 8; j++) {
                int cl = wn + j * 8 + gc * 2;
                float2 bb = *(const float2*)&bias[n0 + cl];
                tsf[(cl + 0) * TLD + r0]     = c[i][j][0] + bb.x;
                tsf[(cl + 1) * TLD + r0]     = c[i][j][1] + bb.y;
                tsf[(cl + 0) * TLD + r0 + 8] = c[i][j][2] + bb.x;
                tsf[(cl + 1) * TLD + r0 + 8] = c[i][j][3] + bb.y;
            }
        }
        __syncthreads();
        const int b = m0 >> 12;
        const int t0 = m0 & (SEQ - 1);
        __half* Vt = g_Vt + (size_t)b * DMODEL * SEQ;
        #pragma unroll 4
        for (int d = 0; d < 128; d++) {
            Vt[(size_t)(n0 + d) * SEQ + t0 + tid] =
                __float2half_rn(tsf[d * TLD + tid]);
        }
    }
}

// ---------------------------------------------------------------------------
// Kernel 2: scores S = Q @ K^T * (1/32), causal block skip (fp32 out)
// ---------------------------------------------------------------------------
__global__ __launch_bounds__(GTHREADS, 2)
void scores_kernel()
{
    const int b  = blockIdx.z;
    const int m0 = blockIdx.y * BM;
    const int n0 = blockIdx.x * BN;
    if (n0 > m0) return;   // fully masked block

    const __half* Q  = g_QKVh + (size_t)b * SEQ * DMODEL;
    const __half* Km = g_QKVh + (size_t)MTOT * DMODEL + (size_t)b * SEQ * DMODEL;
    float* out = g_S + (size_t)b * SEQ * SEQ;

    const int tid  = threadIdx.x;
    const int lane = tid & 31;
    const int warp = tid >> 5;
    const int wm = (warp & 1) * 64;
    const int wn = (warp >> 1) * 64;

    float c[4][8][4];
    ZERO_ACC(c)

    nt_gemm_h(Q, Km, DMODEL, DMODEL, m0, n0, DMODEL / BK, c, tid, wm, wn, lane);

    const int gr = lane >> 2, gc = lane & 3;
    #pragma unroll
    for (int i = 0; i < 4; i++) {
        int r0 = m0 + wm + i * 16 + gr;
        #pragma unroll
        for (int j = 0; j < 8; j++) {
            int cn = n0 + wn + j * 8 + gc * 2;
            *(float2*)&out[(size_t)r0 * SEQ + cn] =
                make_float2(c[i][j][0] * SCALE_INV, c[i][j][1] * SCALE_INV);
            *(float2*)&out[(size_t)(r0 + 8) * SEQ + cn] =
                make_float2(c[i][j][2] * SCALE_INV, c[i][j][3] * SCALE_INV);
        }
    }
}

// ---------------------------------------------------------------------------
// Kernel 3: softmax, no max-subtraction (|s| <= 32 by Cauchy-Schwarz).
// ---------------------------------------------------------------------------
__global__ __launch_bounds__(256)
void softmax_kernel()
{
    const int r = blockIdx.x;
    const int b = r >> 12;
    const int q = r & (SEQ - 1);
    const float* row = g_S + (size_t)b * SEQ * SEQ + (size_t)q * SEQ;
    __half* prow = g_P + (size_t)b * SEQ * SEQ + (size_t)q * SEQ;
    const int len = q + 1;
    const int tid = threadIdx.x;

    __shared__ float red[256];

    float e[16];
    float sum = 0.0f;
    #pragma unroll
    for (int i = 0; i < 16; i++) {
        const int k = tid + i * 256;
        if (k < len) {
            e[i] = __expf(row[k]);
            sum += e[i];
        }
    }
    red[tid] = sum;
    __syncthreads();
    #pragma unroll
    for (int s = 128; s > 0; s >>= 1) {
        if (tid < s) red[tid] += red[tid + s];
        __syncthreads();
    }
    const float inv = 1.0f / red[0];

    #pragma unroll
    for (int i = 0; i < 16; i++) {
        const int k = tid + i * 256;
        if (k < len)
            prow[k] = __float2half_rn(e[i] * inv);
    }
    const int zf_end = (q | 127) + 1;
    for (int k = len + tid; k < zf_end; k += 256)
        prow[k] = __ushort_as_half(0);
}

// ---------------------------------------------------------------------------
// Kernel 4: O = P @ Vt^T  (NT fp16, causal k-truncation, heavy-first order)
// ---------------------------------------------------------------------------
__global__ __launch_bounds__(GTHREADS, 2)
void pv_kernel(float* __restrict__ out_all)
{
    const int b  = blockIdx.z;
    const int m0 = ((int)(SEQ / BM) - 1 - (int)blockIdx.y) * BM;
    const int n0 = blockIdx.x * BN;

    const __half* P  = g_P  + (size_t)b * SEQ * SEQ;
    const __half* Vt = g_Vt + (size_t)b * DMODEL * SEQ;
    float* out = out_all + (size_t)b * SEQ * DMODEL;

    const int tid  = threadIdx.x;
    const int lane = tid & 31;
    const int warp = tid >> 5;
    const int wm = (warp & 1) * 64;
    const int wn = (warp >> 1) * 64;

    float c[4][8][4];
    ZERO_ACC(c)

    const int kt = (m0 + BM) / BK;
    nt_gemm_h(P, Vt, SEQ, SEQ, m0, n0, kt, c, tid, wm, wn, lane);

    const int gr = lane >> 2, gc = lane & 3;
    #pragma unroll
    for (int i = 0; i < 4; i++) {
        int r0 = m0 + wm + i * 16 + gr;
        #pragma unroll
        for (int j = 0; j < 8; j++) {
            int cn = n0 + wn + j * 8 + gc * 2;
            *(float2*)&out[(size_t)r0 * DMODEL + cn] =
                make_float2(c[i][j][0], c[i][j][1]);
            *(float2*)&out[(size_t)(r0 + 8) * DMODEL + cn] =
                make_float2(c[i][j][2], c[i][j][3]);
        }
    }
}

// ---------------------------------------------------------------------------
extern "C" void kernel_launch(void* const* d_in, const int* in_sizes, int n_in,
                              void* d_out, int out_size)
{
    const float* x  = (const float*)d_in[0];
    const float* Wq = (const float*)d_in[1];
    const float* bq = (const float*)d_in[2];
    const float* Wk = (const float*)d_in[3];
    const float* bk = (const float*)d_in[4];
    const float* Wv = (const float*)d_in[5];
    const float* bv = (const float*)d_in[6];
    float* out = (float*)d_out;

    cudaFuncSetAttribute(qkv_kernel,    cudaFuncAttributeMaxDynamicSharedMemorySize, SMEM_BYTES);
    cudaFuncSetAttribute(scores_kernel, cudaFuncAttributeMaxDynamicSharedMemorySize, SMEM_BYTES);
    cudaFuncSetAttribute(pv_kernel,     cudaFuncAttributeMaxDynamicSharedMemorySize, SMEM_BYTES);

    __half* pX = nullptr;
    cudaGetSymbolAddress((void**)&pX, g_Xh);

    {   // 0) fp16 conversion of x and the three W's
        const int n4x = (MTOT * DMODEL) / 4;
        const int n4w = (DMODEL * DMODEL) / 4;
        roundh_kernel<<<(n4x + 255) / 256, 256>>>(x, pX, n4x);
        dim3 gw((n4w + 255) / 256, 3);
        roundhW_kernel<<<gw, 256>>>(Wq, Wk, Wv, n4w);
    }
    {   // 1) QKV projections (V written transposed to g_Vt)
        dim3 grid(DMODEL / BN, MTOT / BM, 3);    // (8, 128, 3)
        qkv_kernel<<<grid, GTHREADS, SMEM_BYTES>>>(bq, bk, bv);
    }
    {   // 2) scores
        dim3 grid(SEQ / BN, SEQ / BM, BATCH);    // (32, 32, 4)
        scores_kernel<<<grid, GTHREADS, SMEM_BYTES>>>();
    }
    {   // 3) softmax -> P (half)
        softmax_kernel<<<MTOT, 256>>>();
    }
    {   // 4) P @ V
        dim3 grid(DMODEL / BN, SEQ / BM, BATCH); // (8, 32, 4)
        pv_kernel<<<grid, GTHREADS, SMEM_BYTES>>>(out);
    }
}

// round 15
// speedup vs baseline: 1.5302x; 1.5302x over previous
#include <cuda_runtime.h>
#include <cuda_fp16.h>
#include <math.h>
#include <stdint.h>

// Problem constants
#define BATCH 4
#define SEQ   4096
#define DMODEL 1024
#define MTOT  (BATCH * SEQ)          // 16384
#define SCALE_INV (1.0f / 32.0f)     // 1/sqrt(1024)

// GEMM tile config (fp16 NT, mma.sync m16n8k16, 4 warps x (64x64) warp tiles)
#define BM 128
#define BN 128
#define BK 64
#define GTHREADS 128
#define NSTAGE 3
#define LDH   72
#define LDH32 36
#define ROWB  144
#define TILE_BYTES (128 * ROWB)       // 18432
#define STAGE_BYTES (2 * TILE_BYTES)  // 36864
#define SMEM_BYTES (NSTAGE * STAGE_BYTES)  // 110592
#define TLD 132                       // fp32 transpose-stage stride (4 mod 32)
#define NTILES 32                     // SEQ / BN

// Scratch
__device__ __half g_Xh[MTOT * DMODEL];                     // 32 MB  half(x)
__device__ __half g_Wh[3 * DMODEL * DMODEL];               // 6 MB   half(W)
__device__ __half g_QKVh[2 * MTOT * DMODEL];               // 64 MB  half Q,K
__device__ __half g_Vt[(size_t)BATCH * DMODEL * SEQ];      // 32 MB  V transposed [b][d][t]
__device__ __half g_P[(size_t)BATCH * SEQ * SEQ];          // 128 MB unnormalized exp(s) half
__device__ float  g_ps[(size_t)MTOT * NTILES];             // 2 MB   per-tile row partial sums
__device__ float  g_inv[MTOT];                             // 64 KB  1/rowsum

// ---------------------------------------------------------------------------
// Helpers
// ---------------------------------------------------------------------------
__device__ __forceinline__ uint32_t smem_u32(const void* p) {
    return (uint32_t)__cvta_generic_to_shared(p);
}
__device__ __forceinline__ void cp_async16(uint32_t s, const void* g) {
    asm volatile("cp.async.cg.shared.global [%0], [%1], 16;" :: "r"(s), "l"(g));
}
#define CP_COMMIT() asm volatile("cp.async.commit_group;")
#define CP_WAIT1()  asm volatile("cp.async.wait_group 1;")

__device__ __forceinline__ void mma_f16(float* c, const uint32_t* a, const uint32_t* b) {
    asm volatile(
        "mma.sync.aligned.m16n8k16.row.col.f32.f16.f16.f32 "
        "{%0,%1,%2,%3}, {%4,%5,%6,%7}, {%8,%9}, {%0,%1,%2,%3};"
        : "+f"(c[0]), "+f"(c[1]), "+f"(c[2]), "+f"(c[3])
        : "r"(a[0]), "r"(a[1]), "r"(a[2]), "r"(a[3]), "r"(b[0]), "r"(b[1]));
}

// Fill one 128x64-half tile (NT: rows contiguous in K) into stage buffer.
__device__ __forceinline__ void cpa_h(uint32_t Sdst, const __half* G,
                                      int row0, int k0, int ldg, int tid) {
    #pragma unroll
    for (int i = 0; i < 8; i++) {
        int f = tid + i * GTHREADS;
        int row = f >> 3;
        int cb = (f & 7) * 16;
        cp_async16(Sdst + (uint32_t)(row * ROWB + cb),
                   &G[(size_t)(row0 + row) * ldg + k0 + (cb >> 1)]);
    }
}

// MMA over one BK=64 chunk, 64x64 warp tile. Scalar LDS fragments (proven fastest).
__device__ __forceinline__ void mma_block_h(const uint32_t* Au, const uint32_t* Bu,
                                            float c[4][8][4], int wm, int wn, int lane) {
    const int gr = lane >> 2;
    const int gc = lane & 3;
    #pragma unroll
    for (int ks = 0; ks < 4; ks++) {
        const int ko = ks * 8 + gc;
        uint32_t a[4][4], b[8][2];
        #pragma unroll
        for (int i = 0; i < 4; i++) {
            const int r  = (wm + i * 16 + gr) * LDH32;
            const int r8 = r + 8 * LDH32;
            a[i][0] = Au[r + ko];
            a[i][1] = Au[r8 + ko];
            a[i][2] = Au[r + ko + 4];
            a[i][3] = Au[r8 + ko + 4];
        }
        #pragma unroll
        for (int j = 0; j < 8; j++) {
            const int rb = (wn + j * 8 + gr) * LDH32;
            b[j][0] = Bu[rb + ko];
            b[j][1] = Bu[rb + ko + 4];
        }
        #pragma unroll
        for (int i = 0; i < 4; i++)
            #pragma unroll
            for (int j = 0; j < 8; j++)
                mma_f16(c[i][j], a[i], b[j]);
    }
}

// Shared NT fp16 mainloop (one barrier/iter, early next-next-stage prefetch).
__device__ __forceinline__ void nt_gemm_h(const __half* A, const __half* B,
                                          int ldga, int ldgb, int m0, int n0, int kt,
                                          float c[4][8][4], int tid, int wm, int wn, int lane) {
    extern __shared__ __align__(16) unsigned char dsm[];
    const uint32_t sb = smem_u32(dsm);

    #pragma unroll
    for (int s = 0; s < NSTAGE - 1; s++) {
        cpa_h(sb + s * STAGE_BYTES,              A, m0, s * BK, ldga, tid);
        cpa_h(sb + s * STAGE_BYTES + TILE_BYTES, B, n0, s * BK, ldgb, tid);
        CP_COMMIT();
    }
    for (int it = 0; it < kt; it++) {
        CP_WAIT1();
        __syncthreads();
        const int nc = it + NSTAGE - 1;
        if (nc < kt) {
            const int nb = nc % NSTAGE;
            cpa_h(sb + nb * STAGE_BYTES,              A, m0, nc * BK, ldga, tid);
            cpa_h(sb + nb * STAGE_BYTES + TILE_BYTES, B, n0, nc * BK, ldgb, tid);
        }
        CP_COMMIT();
        const int buf = it % NSTAGE;
        const uint32_t* Au = (const uint32_t*)(dsm + buf * STAGE_BYTES);
        const uint32_t* Bu = (const uint32_t*)(dsm + buf * STAGE_BYTES + TILE_BYTES);
        mma_block_h(Au, Bu, c, wm, wn, lane);
    }
}

#define ZERO_ACC(c)                                   \
    _Pragma("unroll")                                 \
    for (int i = 0; i < 4; i++)                       \
        _Pragma("unroll")                             \
        for (int j = 0; j < 8; j++)                   \
            _Pragma("unroll")                         \
            for (int t = 0; t < 4; t++) c[i][j][t] = 0.0f;

// ---------------------------------------------------------------------------
// Kernel 0a/0b: fp32 -> fp16 convert (x; and the three W's in one launch)
// ---------------------------------------------------------------------------
__global__ __launch_bounds__(256)
void roundh_kernel(const float* __restrict__ in, __half* __restrict__ out, int n4)
{
    int i = blockIdx.x * 256 + threadIdx.x;
    if (i < n4) {
        float4 v = ((const float4*)in)[i];
        __half2 h0 = __floats2half2_rn(v.x, v.y);
        __half2 h1 = __floats2half2_rn(v.z, v.w);
        ((uint2*)out)[i] = make_uint2(*(uint32_t*)&h0, *(uint32_t*)&h1);
    }
}

__global__ __launch_bounds__(256)
void roundhW_kernel(const float* __restrict__ Wq, const float* __restrict__ Wk,
                    const float* __restrict__ Wv, int n4)
{
    const int z = blockIdx.y;
    const float* in = (z == 0) ? Wq : (z == 1) ? Wk : Wv;
    __half* out = g_Wh + (size_t)z * DMODEL * DMODEL;
    int i = blockIdx.x * 256 + threadIdx.x;
    if (i < n4) {
        float4 v = ((const float4*)in)[i];
        __half2 h0 = __floats2half2_rn(v.x, v.y);
        __half2 h1 = __floats2half2_rn(v.z, v.w);
        ((uint2*)out)[i] = make_uint2(*(uint32_t*)&h0, *(uint32_t*)&h1);
    }
}

// ---------------------------------------------------------------------------
// Kernel 1: QKV projection. z<2: out = half(x@W^T + b) to g_QKVh.
//           z==2: V tile transposed through smem -> g_Vt only.
// ---------------------------------------------------------------------------
__global__ __launch_bounds__(GTHREADS, 2)
void qkv_kernel(const float* __restrict__ bq,
                const float* __restrict__ bk,
                const float* __restrict__ bv)
{
    const int z = blockIdx.z;
    const __half* W    = g_Wh + (size_t)z * DMODEL * DMODEL;
    const float*  bias = (z == 0) ? bq : (z == 1) ? bk : bv;

    const int tid  = threadIdx.x;
    const int lane = tid & 31;
    const int warp = tid >> 5;
    const int wm = (warp & 1) * 64;
    const int wn = (warp >> 1) * 64;
    const int m0 = blockIdx.y * BM;
    const int n0 = blockIdx.x * BN;

    float c[4][8][4];
    ZERO_ACC(c)

    nt_gemm_h(g_Xh, W, DMODEL, DMODEL, m0, n0, DMODEL / BK, c, tid, wm, wn, lane);

    const int gr = lane >> 2, gc = lane & 3;
    if (z < 2) {
        __half* out = g_QKVh + (size_t)z * (MTOT * DMODEL);
        #pragma unroll
        for (int i = 0; i < 4; i++) {
            int r0 = m0 + wm + i * 16 + gr;
            #pragma unroll
            for (int j = 0; j < 8; j++) {
                int cn = n0 + wn + j * 8 + gc * 2;
                float2 bb = *(const float2*)&bias[cn];
                __half2 h0 = __floats2half2_rn(c[i][j][0] + bb.x, c[i][j][1] + bb.y);
                __half2 h1 = __floats2half2_rn(c[i][j][2] + bb.x, c[i][j][3] + bb.y);
                *(__half2*)&out[(size_t)r0 * DMODEL + cn] = h0;
                *(__half2*)&out[(size_t)(r0 + 8) * DMODEL + cn] = h1;
            }
        }
    } else {
        // V: stage fp32 tile transposed in smem, then coalesced half writes to Vt.
        extern __shared__ __align__(16) unsigned char dsm[];
        float* tsf = (float*)dsm;   // 128 x TLD floats
        __syncthreads();            // mainloop smem reads done
        #pragma unroll
        for (int i = 0; i < 4; i++) {
            int r0 = wm + i * 16 + gr;
            #pragma unroll
            for (int j = 0; j < 8; j++) {
                int cl = wn + j * 8 + gc * 2;
                float2 bb = *(const float2*)&bias[n0 + cl];
                tsf[(cl + 0) * TLD + r0]     = c[i][j][0] + bb.x;
                tsf[(cl + 1) * TLD + r0]     = c[i][j][1] + bb.y;
                tsf[(cl + 0) * TLD + r0 + 8] = c[i][j][2] + bb.x;
                tsf[(cl + 1) * TLD + r0 + 8] = c[i][j][3] + bb.y;
            }
        }
        __syncthreads();
        const int b = m0 >> 12;
        const int t0 = m0 & (SEQ - 1);
        __half* Vt = g_Vt + (size_t)b * DMODEL * SEQ;
        #pragma unroll 4
        for (int d = 0; d < 128; d++) {
            Vt[(size_t)(n0 + d) * SEQ + t0 + tid] =
                __float2half_rn(tsf[d * TLD + tid]);
        }
    }
}

// ---------------------------------------------------------------------------
// Kernel 2: fused scores+softmax-numerator.
// Writes P = half(exp(QK^T/32)) (causally masked), and per-tile row sums
// to g_ps. No S array, no separate softmax pass. No max-subtraction:
// |s| <= 32 by Cauchy-Schwarz (fp32 exp safe); half-store clamped.
// ---------------------------------------------------------------------------
__global__ __launch_bounds__(GTHREADS, 2)
void scores_kernel()
{
    const int b  = blockIdx.z;
    const int m0 = blockIdx.y * BM;
    const int n0 = blockIdx.x * BN;
    if (n0 > m0) return;   // fully masked block

    const __half* Q  = g_QKVh + (size_t)b * SEQ * DMODEL;
    const __half* Km = g_QKVh + (size_t)MTOT * DMODEL + (size_t)b * SEQ * DMODEL;
    __half* P = g_P + (size_t)b * SEQ * SEQ;

    const int tid  = threadIdx.x;
    const int lane = tid & 31;
    const int warp = tid >> 5;
    const int wm = (warp & 1) * 64;
    const int wn = (warp >> 1) * 64;

    float c[4][8][4];
    ZERO_ACC(c)

    nt_gemm_h(Q, Km, DMODEL, DMODEL, m0, n0, DMODEL / BK, c, tid, wm, wn, lane);

    extern __shared__ __align__(16) unsigned char dsm[];
    float* sarr = (float*)dsm;          // 128 row partials (reuses stage smem)
    __syncthreads();                    // all mainloop smem reads complete
    if (tid < 128) sarr[tid] = 0.0f;
    __syncthreads();

    const int gr = lane >> 2, gc = lane & 3;
    float rs[8];
    #pragma unroll
    for (int i = 0; i < 4; i++) {
        const int q0 = m0 + wm + i * 16 + gr;     // global q rows
        const int q1 = q0 + 8;
        float s0 = 0.0f, s1 = 0.0f;
        #pragma unroll
        for (int j = 0; j < 8; j++) {
            const int cn = n0 + wn + j * 8 + gc * 2;
            float e0 = (cn     <= q0) ? fminf(__expf(c[i][j][0] * SCALE_INV), 60000.f) : 0.0f;
            float e1 = (cn + 1 <= q0) ? fminf(__expf(c[i][j][1] * SCALE_INV), 60000.f) : 0.0f;
            float e2 = (cn     <= q1) ? fminf(__expf(c[i][j][2] * SCALE_INV), 60000.f) : 0.0f;
            float e3 = (cn + 1 <= q1) ? fminf(__expf(c[i][j][3] * SCALE_INV), 60000.f) : 0.0f;
            s0 += e0 + e1;
            s1 += e2 + e3;
            __half2 h0 = __floats2half2_rn(e0, e1);
            __half2 h1 = __floats2half2_rn(e2, e3);
            *(__half2*)&P[(size_t)q0 * SEQ + cn] = h0;
            *(__half2*)&P[(size_t)q1 * SEQ + cn] = h1;
        }
        rs[2 * i] = s0;
        rs[2 * i + 1] = s1;
    }
    // reduce over the 4 gc lanes (bits 0,1 of lane)
    #pragma unroll
    for (int i = 0; i < 8; i++) {
        rs[i] += __shfl_xor_sync(0xffffffffu, rs[i], 1);
        rs[i] += __shfl_xor_sync(0xffffffffu, rs[i], 2);
    }
    if (gc == 0) {
        #pragma unroll
        for (int i = 0; i < 4; i++) {
            atomicAdd(&sarr[wm + i * 16 + gr],     rs[2 * i]);
            atomicAdd(&sarr[wm + i * 16 + gr + 8], rs[2 * i + 1]);
        }
    }
    __syncthreads();
    if (tid < 128)
        g_ps[((size_t)b * SEQ + m0 + tid) * NTILES + (n0 >> 7)] = sarr[tid];
}

// ---------------------------------------------------------------------------
// Kernel 3: deterministic row-sum finalize: g_inv = 1 / sum(partials)
// ---------------------------------------------------------------------------
__global__ __launch_bounds__(256)
void rowsum_kernel()
{
    const int idx = blockIdx.x * 256 + threadIdx.x;   // 0..MTOT-1
    const int q = idx & (SEQ - 1);
    const float* ps = &g_ps[(size_t)idx * NTILES];
    const int nt = (q >> 7) + 1;
    float s = 0.0f;
    for (int t = 0; t < nt; t++) s += ps[t];
    g_inv[idx] = 1.0f / s;
}

// ---------------------------------------------------------------------------
// Kernel 4: O = (Pexp @ Vt^T) * inv[row]  (NT fp16, causal k-truncation)
// ---------------------------------------------------------------------------
__global__ __launch_bounds__(GTHREADS, 2)
void pv_kernel(float* __restrict__ out_all)
{
    const int b  = blockIdx.z;
    const int m0 = ((int)(SEQ / BM) - 1 - (int)blockIdx.y) * BM;  // heavy-first
    const int n0 = blockIdx.x * BN;

    const __half* P  = g_P  + (size_t)b * SEQ * SEQ;
    const __half* Vt = g_Vt + (size_t)b * DMODEL * SEQ;
    const float* inv = g_inv + (size_t)b * SEQ;
    float* out = out_all + (size_t)b * SEQ * DMODEL;

    const int tid  = threadIdx.x;
    const int lane = tid & 31;
    const int warp = tid >> 5;
    const int wm = (warp & 1) * 64;
    const int wn = (warp >> 1) * 64;

    float c[4][8][4];
    ZERO_ACC(c)

    const int kt = (m0 + BM) / BK;
    nt_gemm_h(P, Vt, SEQ, SEQ, m0, n0, kt, c, tid, wm, wn, lane);

    const int gr = lane >> 2, gc = lane & 3;
    #pragma unroll
    for (int i = 0; i < 4; i++) {
        int r0 = m0 + wm + i * 16 + gr;
        const float v0 = inv[r0];
        const float v1 = inv[r0 + 8];
        #pragma unroll
        for (int j = 0; j < 8; j++) {
            int cn = n0 + wn + j * 8 + gc * 2;
            *(float2*)&out[(size_t)r0 * DMODEL + cn] =
                make_float2(c[i][j][0] * v0, c[i][j][1] * v0);
            *(float2*)&out[(size_t)(r0 + 8) * DMODEL + cn] =
                make_float2(c[i][j][2] * v1, c[i][j][3] * v1);
        }
    }
}

// ---------------------------------------------------------------------------
extern "C" void kernel_launch(void* const* d_in, const int* in_sizes, int n_in,
                              void* d_out, int out_size)
{
    const float* x  = (const float*)d_in[0];
    const float* Wq = (const float*)d_in[1];
    const float* bq = (const float*)d_in[2];
    const float* Wk = (const float*)d_in[3];
    const float* bk = (const float*)d_in[4];
    const float* Wv = (const float*)d_in[5];
    const float* bv = (const float*)d_in[6];
    float* out = (float*)d_out;

    cudaFuncSetAttribute(qkv_kernel,    cudaFuncAttributeMaxDynamicSharedMemorySize, SMEM_BYTES);
    cudaFuncSetAttribute(scores_kernel, cudaFuncAttributeMaxDynamicSharedMemorySize, SMEM_BYTES);
    cudaFuncSetAttribute(pv_kernel,     cudaFuncAttributeMaxDynamicSharedMemorySize, SMEM_BYTES);

    __half* pX = nullptr;
    cudaGetSymbolAddress((void**)&pX, g_Xh);

    {   // 0) fp16 conversion of x and the three W's
        const int n4x = (MTOT * DMODEL) / 4;
        const int n4w = (DMODEL * DMODEL) / 4;
        roundh_kernel<<<(n4x + 255) / 256, 256>>>(x, pX, n4x);
        dim3 gw((n4w + 255) / 256, 3);
        roundhW_kernel<<<gw, 256>>>(Wq, Wk, Wv, n4w);
    }
    {   // 1) QKV projections (V written transposed to g_Vt)
        dim3 grid(DMODEL / BN, MTOT / BM, 3);    // (8, 128, 3)
        qkv_kernel<<<grid, GTHREADS, SMEM_BYTES>>>(bq, bk, bv);
    }
    {   // 2) fused scores + exp + partial row sums
        dim3 grid(SEQ / BN, SEQ / BM, BATCH);    // (32, 32, 4)
        scores_kernel<<<grid, GTHREADS, SMEM_BYTES>>>();
    }
    {   // 3) row-sum finalize
        rowsum_kernel<<<MTOT / 256, 256>>>();
    }
    {   // 4) P @ V with per-row normalization
        dim3 grid(DMODEL / BN, SEQ / BM, BATCH); // (8, 32, 4)
        pv_kernel<<<grid, GTHREADS, SMEM_BYTES>>>(out);
    }
}

// round 17
// speedup vs baseline: 1.5343x; 1.0027x over previous
#include <cuda_runtime.h>
#include <cuda_fp16.h>
#include <math.h>
#include <stdint.h>

// Problem constants
#define BATCH 4
#define SEQ   4096
#define DMODEL 1024
#define MTOT  (BATCH * SEQ)          // 16384
#define SCALE_INV (1.0f / 32.0f)     // 1/sqrt(1024)

// GEMM tile config (fp16 NT, mma.sync m16n8k16, 4 warps x (64x64) warp tiles)
#define BM 128
#define BN 128
#define BK 64
#define GTHREADS 128
#define NSTAGE 2
#define LDH   72
#define LDH32 36
#define ROWB  144
#define TILE_BYTES (128 * ROWB)       // 18432
#define STAGE_BYTES (2 * TILE_BYTES)  // 36864
#define SMEM_BYTES (NSTAGE * STAGE_BYTES)  // 73728 -> 3 CTAs/SM
#define TLD 132                       // fp32 transpose-stage stride (4 mod 32)
#define NTILES 32                     // SEQ / BN

// Scratch
__device__ __half g_Xh[MTOT * DMODEL];                     // 32 MB  half(x)
__device__ __half g_Wh[3 * DMODEL * DMODEL];               // 6 MB   half(W)
__device__ __half g_QKVh[2 * MTOT * DMODEL];               // 64 MB  half Q,K
__device__ __half g_Vt[(size_t)BATCH * DMODEL * SEQ];      // 32 MB  V transposed [b][d][t]
__device__ __half g_P[(size_t)BATCH * SEQ * SEQ];          // 128 MB unnormalized exp(s) half
__device__ float  g_ps[(size_t)MTOT * NTILES];             // 2 MB   per-tile row partial sums
__device__ float  g_inv[MTOT];                             // 64 KB  1/rowsum

// ---------------------------------------------------------------------------
// Helpers
// ---------------------------------------------------------------------------
__device__ __forceinline__ uint32_t smem_u32(const void* p) {
    return (uint32_t)__cvta_generic_to_shared(p);
}
__device__ __forceinline__ void cp_async16(uint32_t s, const void* g) {
    asm volatile("cp.async.cg.shared.global [%0], [%1], 16;" :: "r"(s), "l"(g));
}
#define CP_COMMIT() asm volatile("cp.async.commit_group;")
#define CP_WAIT0()  asm volatile("cp.async.wait_group 0;")

__device__ __forceinline__ void mma_f16(float* c, const uint32_t* a, const uint32_t* b) {
    asm volatile(
        "mma.sync.aligned.m16n8k16.row.col.f32.f16.f16.f32 "
        "{%0,%1,%2,%3}, {%4,%5,%6,%7}, {%8,%9}, {%0,%1,%2,%3};"
        : "+f"(c[0]), "+f"(c[1]), "+f"(c[2]), "+f"(c[3])
        : "r"(a[0]), "r"(a[1]), "r"(a[2]), "r"(a[3]), "r"(b[0]), "r"(b[1]));
}

// Fill one 128x64-half tile (NT: rows contiguous in K) into stage buffer.
__device__ __forceinline__ void cpa_h(uint32_t Sdst, const __half* G,
                                      int row0, int k0, int ldg, int tid) {
    #pragma unroll
    for (int i = 0; i < 8; i++) {
        int f = tid + i * GTHREADS;
        int row = f >> 3;
        int cb = (f & 7) * 16;
        cp_async16(Sdst + (uint32_t)(row * ROWB + cb),
                   &G[(size_t)(row0 + row) * ldg + k0 + (cb >> 1)]);
    }
}

// MMA over one BK=64 chunk, 64x64 warp tile. Scalar LDS fragments;
// B loaded just-in-time per n8 tile to minimize live registers.
__device__ __forceinline__ void mma_block_h(const uint32_t* Au, const uint32_t* Bu,
                                            float c[4][8][4], int wm, int wn, int lane) {
    const int gr = lane >> 2;
    const int gc = lane & 3;
    #pragma unroll
    for (int ks = 0; ks < 4; ks++) {
        const int ko = ks * 8 + gc;
        uint32_t a[4][4];
        #pragma unroll
        for (int i = 0; i < 4; i++) {
            const int r  = (wm + i * 16 + gr) * LDH32;
            const int r8 = r + 8 * LDH32;
            a[i][0] = Au[r + ko];
            a[i][1] = Au[r8 + ko];
            a[i][2] = Au[r + ko + 4];
            a[i][3] = Au[r8 + ko + 4];
        }
        #pragma unroll
        for (int j = 0; j < 8; j++) {
            uint32_t b[2];
            const int rb = (wn + j * 8 + gr) * LDH32;
            b[0] = Bu[rb + ko];
            b[1] = Bu[rb + ko + 4];
            #pragma unroll
            for (int i = 0; i < 4; i++)
                mma_f16(c[i][j], a[i], b);
        }
    }
}

// Shared NT fp16 mainloop, 2-stage double buffer, one barrier per iter.
// Schedule: wait own stage-it copies -> barrier (publish + prior readers of
// the other buffer are done) -> fill buf (it+1)&1 -> MMA buf it&1.
__device__ __forceinline__ void nt_gemm_h(const __half* A, const __half* B,
                                          int ldga, int ldgb, int m0, int n0, int kt,
                                          float c[4][8][4], int tid, int wm, int wn, int lane) {
    extern __shared__ __align__(16) unsigned char dsm[];
    const uint32_t sb = smem_u32(dsm);

    cpa_h(sb,              A, m0, 0, ldga, tid);
    cpa_h(sb + TILE_BYTES, B, n0, 0, ldgb, tid);
    CP_COMMIT();

    for (int it = 0; it < kt; it++) {
        CP_WAIT0();
        __syncthreads();
        const int nc = it + 1;
        if (nc < kt) {
            const int nb = nc & 1;
            cpa_h(sb + nb * STAGE_BYTES,              A, m0, nc * BK, ldga, tid);
            cpa_h(sb + nb * STAGE_BYTES + TILE_BYTES, B, n0, nc * BK, ldgb, tid);
            CP_COMMIT();
        }
        const int buf = it & 1;
        const uint32_t* Au = (const uint32_t*)(dsm + buf * STAGE_BYTES);
        const uint32_t* Bu = (const uint32_t*)(dsm + buf * STAGE_BYTES + TILE_BYTES);
        mma_block_h(Au, Bu, c, wm, wn, lane);
    }
}

#define ZERO_ACC(c)                                   \
    _Pragma("unroll")                                 \
    for (int i = 0; i < 4; i++)                       \
        _Pragma("unroll")                             \
        for (int j = 0; j < 8; j++)                   \
            _Pragma("unroll")                         \
            for (int t = 0; t < 4; t++) c[i][j][t] = 0.0f;

// ---------------------------------------------------------------------------
// Kernel 0a/0b: fp32 -> fp16 convert (x; and the three W's in one launch)
// ---------------------------------------------------------------------------
__global__ __launch_bounds__(256)
void roundh_kernel(const float* __restrict__ in, __half* __restrict__ out, int n4)
{
    int i = blockIdx.x * 256 + threadIdx.x;
    if (i < n4) {
        float4 v = ((const float4*)in)[i];
        __half2 h0 = __floats2half2_rn(v.x, v.y);
        __half2 h1 = __floats2half2_rn(v.z, v.w);
        ((uint2*)out)[i] = make_uint2(*(uint32_t*)&h0, *(uint32_t*)&h1);
    }
}

__global__ __launch_bounds__(256)
void roundhW_kernel(const float* __restrict__ Wq, const float* __restrict__ Wk,
                    const float* __restrict__ Wv, int n4)
{
    const int z = blockIdx.y;
    const float* in = (z == 0) ? Wq : (z == 1) ? Wk : Wv;
    __half* out = g_Wh + (size_t)z * DMODEL * DMODEL;
    int i = blockIdx.x * 256 + threadIdx.x;
    if (i < n4) {
        float4 v = ((const float4*)in)[i];
        __half2 h0 = __floats2half2_rn(v.x, v.y);
        __half2 h1 = __floats2half2_rn(v.z, v.w);
        ((uint2*)out)[i] = make_uint2(*(uint32_t*)&h0, *(uint32_t*)&h1);
    }
}

// ---------------------------------------------------------------------------
// Kernel 1: QKV projection. z<2: out = half(x@W^T + b) to g_QKVh.
//           z==2: V tile transposed through smem -> g_Vt only.
// ---------------------------------------------------------------------------
__global__ __launch_bounds__(GTHREADS, 3)
void qkv_kernel(const float* __restrict__ bq,
                const float* __restrict__ bk,
                const float* __restrict__ bv)
{
    const int z = blockIdx.z;
    const __half* W    = g_Wh + (size_t)z * DMODEL * DMODEL;
    const float*  bias = (z == 0) ? bq : (z == 1) ? bk : bv;

    const int tid  = threadIdx.x;
    const int lane = tid & 31;
    const int warp = tid >> 5;
    const int wm = (warp & 1) * 64;
    const int wn = (warp >> 1) * 64;
    const int m0 = blockIdx.y * BM;
    const int n0 = blockIdx.x * BN;

    float c[4][8][4];
    ZERO_ACC(c)

    nt_gemm_h(g_Xh, W, DMODEL, DMODEL, m0, n0, DMODEL / BK, c, tid, wm, wn, lane);

    const int gr = lane >> 2, gc = lane & 3;
    if (z < 2) {
        __half* out = g_QKVh + (size_t)z * (MTOT * DMODEL);
        #pragma unroll
        for (int i = 0; i < 4; i++) {
            int r0 = m0 + wm + i * 16 + gr;
            #pragma unroll
            for (int j = 0; j < 8; j++) {
                int cn = n0 + wn + j * 8 + gc * 2;
                float2 bb = *(const float2*)&bias[cn];
                __half2 h0 = __floats2half2_rn(c[i][j][0] + bb.x, c[i][j][1] + bb.y);
                __half2 h1 = __floats2half2_rn(c[i][j][2] + bb.x, c[i][j][3] + bb.y);
                *(__half2*)&out[(size_t)r0 * DMODEL + cn] = h0;
                *(__half2*)&out[(size_t)(r0 + 8) * DMODEL + cn] = h1;
            }
        }
    } else {
        // V: stage fp32 tile transposed in smem, then coalesced half writes to Vt.
        extern __shared__ __align__(16) unsigned char dsm[];
        float* tsf = (float*)dsm;   // 128 x TLD floats = 67.6 KB (fits 73.7 KB)
        __syncthreads();            // mainloop smem reads done
        #pragma unroll
        for (int i = 0; i < 4; i++) {
            int r0 = wm + i * 16 + gr;
            #pragma unroll
            for (int j = 0; j < 8; j++) {
                int cl = wn + j * 8 + gc * 2;
                float2 bb = *(const float2*)&bias[n0 + cl];
                tsf[(cl + 0) * TLD + r0]     = c[i][j][0] + bb.x;
                tsf[(cl + 1) * TLD + r0]     = c[i][j][1] + bb.y;
                tsf[(cl + 0) * TLD + r0 + 8] = c[i][j][2] + bb.x;
                tsf[(cl + 1) * TLD + r0 + 8] = c[i][j][3] + bb.y;
            }
        }
        __syncthreads();
        const int b = m0 >> 12;
        const int t0 = m0 & (SEQ - 1);
        __half* Vt = g_Vt + (size_t)b * DMODEL * SEQ;
        #pragma unroll 4
        for (int d = 0; d < 128; d++) {
            Vt[(size_t)(n0 + d) * SEQ + t0 + tid] =
                __float2half_rn(tsf[d * TLD + tid]);
        }
    }
}

// ---------------------------------------------------------------------------
// Kernel 2: fused scores+softmax-numerator.
// Writes P = half(exp(QK^T/32)) (causally masked), and per-tile row sums
// to g_ps. No max-subtraction: |s| <= 32 by Cauchy-Schwarz.
// ---------------------------------------------------------------------------
__global__ __launch_bounds__(GTHREADS, 3)
void scores_kernel()
{
    const int b  = blockIdx.z;
    const int m0 = blockIdx.y * BM;
    const int n0 = blockIdx.x * BN;
    if (n0 > m0) return;   // fully masked block

    const __half* Q  = g_QKVh + (size_t)b * SEQ * DMODEL;
    const __half* Km = g_QKVh + (size_t)MTOT * DMODEL + (size_t)b * SEQ * DMODEL;
    __half* P = g_P + (size_t)b * SEQ * SEQ;

    const int tid  = threadIdx.x;
    const int lane = tid & 31;
    const int warp = tid >> 5;
    const int wm = (warp & 1) * 64;
    const int wn = (warp >> 1) * 64;

    float c[4][8][4];
    ZERO_ACC(c)

    nt_gemm_h(Q, Km, DMODEL, DMODEL, m0, n0, DMODEL / BK, c, tid, wm, wn, lane);

    extern __shared__ __align__(16) unsigned char dsm[];
    float* sarr = (float*)dsm;          // 128 row partials (reuses stage smem)
    __syncthreads();                    // all mainloop smem reads complete
    if (tid < 128) sarr[tid] = 0.0f;
    __syncthreads();

    const int gr = lane >> 2, gc = lane & 3;
    float rs[8];
    #pragma unroll
    for (int i = 0; i < 4; i++) {
        const int q0 = m0 + wm + i * 16 + gr;     // global q rows
        const int q1 = q0 + 8;
        float s0 = 0.0f, s1 = 0.0f;
        #pragma unroll
        for (int j = 0; j < 8; j++) {
            const int cn = n0 + wn + j * 8 + gc * 2;
            float e0 = (cn     <= q0) ? fminf(__expf(c[i][j][0] * SCALE_INV), 60000.f) : 0.0f;
            float e1 = (cn + 1 <= q0) ? fminf(__expf(c[i][j][1] * SCALE_INV), 60000.f) : 0.0f;
            float e2 = (cn     <= q1) ? fminf(__expf(c[i][j][2] * SCALE_INV), 60000.f) : 0.0f;
            float e3 = (cn + 1 <= q1) ? fminf(__expf(c[i][j][3] * SCALE_INV), 60000.f) : 0.0f;
            s0 += e0 + e1;
            s1 += e2 + e3;
            __half2 h0 = __floats2half2_rn(e0, e1);
            __half2 h1 = __floats2half2_rn(e2, e3);
            *(__half2*)&P[(size_t)q0 * SEQ + cn] = h0;
            *(__half2*)&P[(size_t)q1 * SEQ + cn] = h1;
        }
        rs[2 * i] = s0;
        rs[2 * i + 1] = s1;
    }
    // reduce over the 4 gc lanes (bits 0,1 of lane)
    #pragma unroll
    for (int i = 0; i < 8; i++) {
        rs[i] += __shfl_xor_sync(0xffffffffu, rs[i], 1);
        rs[i] += __shfl_xor_sync(0xffffffffu, rs[i], 2);
    }
    if (gc == 0) {
        #pragma unroll
        for (int i = 0; i < 4; i++) {
            atomicAdd(&sarr[wm + i * 16 + gr],     rs[2 * i]);
            atomicAdd(&sarr[wm + i * 16 + gr + 8], rs[2 * i + 1]);
        }
    }
    __syncthreads();
    if (tid < 128)
        g_ps[((size_t)b * SEQ + m0 + tid) * NTILES + (n0 >> 7)] = sarr[tid];
}

// ---------------------------------------------------------------------------
// Kernel 3: deterministic row-sum finalize: g_inv = 1 / sum(partials)
// ---------------------------------------------------------------------------
__global__ __launch_bounds__(256)
void rowsum_kernel()
{
    const int idx = blockIdx.x * 256 + threadIdx.x;   // 0..MTOT-1
    const int q = idx & (SEQ - 1);
    const float* ps = &g_ps[(size_t)idx * NTILES];
    const int nt = (q >> 7) + 1;
    float s = 0.0f;
    for (int t = 0; t < nt; t++) s += ps[t];
    g_inv[idx] = 1.0f / s;
}

// ---------------------------------------------------------------------------
// Kernel 4: O = (Pexp @ Vt^T) * inv[row]  (NT fp16, causal k-truncation)
// ---------------------------------------------------------------------------
__global__ __launch_bounds__(GTHREADS, 3)
void pv_kernel(float* __restrict__ out_all)
{
    const int b  = blockIdx.z;
    const int m0 = ((int)(SEQ / BM) - 1 - (int)blockIdx.y) * BM;  // heavy-first
    const int n0 = blockIdx.x * BN;

    const __half* P  = g_P  + (size_t)b * SEQ * SEQ;
    const __half* Vt = g_Vt + (size_t)b * DMODEL * SEQ;
    const float* inv = g_inv + (size_t)b * SEQ;
    float* out = out_all + (size_t)b * SEQ * DMODEL;

    const int tid  = threadIdx.x;
    const int lane = tid & 31;
    const int warp = tid >> 5;
    const int wm = (warp & 1) * 64;
    const int wn = (warp >> 1) * 64;

    float c[4][8][4];
    ZERO_ACC(c)

    const int kt = (m0 + BM) / BK;
    nt_gemm_h(P, Vt, SEQ, SEQ, m0, n0, kt, c, tid, wm, wn, lane);

    const int gr = lane >> 2, gc = lane & 3;
    #pragma unroll
    for (int i = 0; i < 4; i++) {
        int r0 = m0 + wm + i * 16 + gr;
        const float v0 = inv[r0];
        const float v1 = inv[r0 + 8];
        #pragma unroll
        for (int j = 0; j < 8; j++) {
            int cn = n0 + wn + j * 8 + gc * 2;
            *(float2*)&out[(size_t)r0 * DMODEL + cn] =
                make_float2(c[i][j][0] * v0, c[i][j][1] * v0);
            *(float2*)&out[(size_t)(r0 + 8) * DMODEL + cn] =
                make_float2(c[i][j][2] * v1, c[i][j][3] * v1);
        }
    }
}

// ---------------------------------------------------------------------------
extern "C" void kernel_launch(void* const* d_in, const int* in_sizes, int n_in,
                              void* d_out, int out_size)
{
    const float* x  = (const float*)d_in[0];
    const float* Wq = (const float*)d_in[1];
    const float* bq = (const float*)d_in[2];
    const float* Wk = (const float*)d_in[3];
    const float* bk = (const float*)d_in[4];
    const float* Wv = (const float*)d_in[5];
    const float* bv = (const float*)d_in[6];
    float* out = (float*)d_out;

    cudaFuncSetAttribute(qkv_kernel,    cudaFuncAttributeMaxDynamicSharedMemorySize, SMEM_BYTES);
    cudaFuncSetAttribute(scores_kernel, cudaFuncAttributeMaxDynamicSharedMemorySize, SMEM_BYTES);
    cudaFuncSetAttribute(pv_kernel,     cudaFuncAttributeMaxDynamicSharedMemorySize, SMEM_BYTES);

    __half* pX = nullptr;
    cudaGetSymbolAddress((void**)&pX, g_Xh);

    {   // 0) fp16 conversion of x and the three W's
        const int n4x = (MTOT * DMODEL) / 4;
        const int n4w = (DMODEL * DMODEL) / 4;
        roundh_kernel<<<(n4x + 255) / 256, 256>>>(x, pX, n4x);
        dim3 gw((n4w + 255) / 256, 3);
        roundhW_kernel<<<gw, 256>>>(Wq, Wk, Wv, n4w);
    }
    {   // 1) QKV projections (V written transposed to g_Vt)
        dim3 grid(DMODEL / BN, MTOT / BM, 3);    // (8, 128, 3)
        qkv_kernel<<<grid, GTHREADS, SMEM_BYTES>>>(bq, bk, bv);
    }
    {   // 2) fused scores + exp + partial row sums
        dim3 grid(SEQ / BN, SEQ / BM, BATCH);    // (32, 32, 4)
        scores_kernel<<<grid, GTHREADS, SMEM_BYTES>>>();
    }
    {   // 3) row-sum finalize
        rowsum_kernel<<<MTOT / 256, 256>>>();
    }
    {   // 4) P @ V with per-row normalization
        dim3 grid(DMODEL / BN, SEQ / BM, BATCH); // (8, 32, 4)
        pv_kernel<<<grid, GTHREADS, SMEM_BYTES>>>(out);
    }
}